// round 3
// baseline (speedup 1.0000x reference)
#include <cuda_runtime.h>
#include <cuda_bf16.h>
#include <math.h>

#define NNODE 100000
#define FIN   512
#define HID   256
#define CLS   64

// ---------------- scratch (static device globals; no allocation) ----------------
__device__ float g_Hm[(size_t)NNODE * HID];   // elu(x@Wm0+bm0)
__device__ float g_Hv[(size_t)NNODE * HID];   // relu(x@Wv0+bv0)
__device__ float g_m64[(size_t)NNODE * CLS];  // mean*attn
__device__ float g_v64[(size_t)NNODE * CLS];  // var*attn^2
__device__ float g_accm[(size_t)NNODE * CLS]; // spmm accumulators
__device__ float g_accv[(size_t)NNODE * CLS];
__device__ int   g_cnt[NNODE];
__device__ float g_dis[NNODE];                // deg^-0.5
__device__ float g_di[NNODE];                 // deg^-1

// ---------------- degree ----------------
__global__ void count_init_kernel(int n) {
    int i = blockIdx.x * blockDim.x + threadIdx.x;
    if (i < n) g_cnt[i] = 1;   // self loop
}

__global__ void count_edges_kernel(const int* __restrict__ src, int e) {
    int i = blockIdx.x * blockDim.x + threadIdx.x;
    if (i < e) atomicAdd(&g_cnt[src[i]], 1);
}

__global__ void make_deg_kernel(int n) {
    int i = blockIdx.x * blockDim.x + threadIdx.x;
    if (i < n) {
        float c = (float)g_cnt[i];           // always >= 1
        g_dis[i] = 1.0f / sqrtf(c);
        g_di[i]  = 1.0f / c;
    }
}

// ---------------- layer 0 GEMM: H = act(X @ W + b) ----------------
// BM=128, BN=128, BK=16, 256 threads, 8x8 micro-tile. blockIdx.z selects path.
#define BM 128
#define BN 128
#define BK 16
#define TM 8
#define TN 8

__global__ __launch_bounds__(256) void gemm0_kernel(
    const float* __restrict__ X,
    const float* __restrict__ Wm, const float* __restrict__ bm,
    const float* __restrict__ Wv, const float* __restrict__ bv,
    int M)
{
    const int K = FIN, NC = HID;
    __shared__ float As[BK][BM];
    __shared__ float Bs[BK][BN];

    int path = blockIdx.z;
    const float* W    = path ? Wv : Wm;
    const float* bias = path ? bv : bm;
    float* H          = path ? g_Hv : g_Hm;

    int rowBase = blockIdx.y * BM;
    int colBase = blockIdx.x * BN;
    int t  = threadIdx.x;
    int tx = t & 15;       // col group (TN=8)
    int ty = t >> 4;       // row group (TM=8)

    float acc[TM][TN];
    #pragma unroll
    for (int i = 0; i < TM; i++)
        #pragma unroll
        for (int j = 0; j < TN; j++) acc[i][j] = 0.0f;

    for (int k0 = 0; k0 < K; k0 += BK) {
        // A tile 128x16 -> As[k][m] (transposed), 512 float4 / 256 thr = 2 each
        #pragma unroll
        for (int l = 0; l < 2; l++) {
            int idx = t + l * 256;
            int r   = idx >> 2;
            int c4  = idx & 3;
            int grow = rowBase + r;
            float4 v = make_float4(0.f, 0.f, 0.f, 0.f);
            if (grow < M)
                v = *(const float4*)(X + (size_t)grow * K + k0 + c4 * 4);
            As[c4 * 4 + 0][r] = v.x;
            As[c4 * 4 + 1][r] = v.y;
            As[c4 * 4 + 2][r] = v.z;
            As[c4 * 4 + 3][r] = v.w;
        }
        // B tile 16x128, 512 float4 / 256 thr = 2 each
        #pragma unroll
        for (int l = 0; l < 2; l++) {
            int idx = t + l * 256;
            int r   = idx >> 5;        // 0..15
            int c4  = idx & 31;        // 0..31
            float4 v = *(const float4*)(W + (size_t)(k0 + r) * NC + colBase + c4 * 4);
            *(float4*)&Bs[r][c4 * 4] = v;
        }
        __syncthreads();

        #pragma unroll
        for (int k = 0; k < BK; k++) {
            float a[TM], b[TN];
            #pragma unroll
            for (int i = 0; i < TM; i++) a[i] = As[k][ty * TM + i];
            #pragma unroll
            for (int j = 0; j < TN; j++) b[j] = Bs[k][tx * TN + j];
            #pragma unroll
            for (int i = 0; i < TM; i++)
                #pragma unroll
                for (int j = 0; j < TN; j++)
                    acc[i][j] += a[i] * b[j];
        }
        __syncthreads();
    }

    #pragma unroll
    for (int i = 0; i < TM; i++) {
        int r = rowBase + ty * TM + i;
        if (r >= M) continue;
        #pragma unroll
        for (int j = 0; j < TN; j++) {
            int c = colBase + tx * TN + j;
            float v = acc[i][j] + bias[c];
            if (path == 0) v = (v > 0.0f) ? v : expm1f(v);   // elu
            else           v = fmaxf(v, 0.0f);               // relu
            H[(size_t)r * NC + c] = v;
        }
    }
}

// ---------------- layer 1 fused: both paths + attn coupling + self-loop init ----
// BM=128 rows, 64 cols, K=256, 256 threads, 8x4 micro-tile per path.
__device__ __forceinline__ void l1_mm_path(
    const float* __restrict__ A, const float* __restrict__ W,
    int rowBase, int M, int tx, int ty,
    float (&acc)[8][4], float (*As)[128], float (*Bs)[64])
{
    const int K = HID, NC = CLS;
    for (int k0 = 0; k0 < K; k0 += 16) {
        int t = ty * 16 + tx;
        #pragma unroll
        for (int l = 0; l < 2; l++) {
            int idx = t + l * 256;
            int r   = idx >> 2;
            int c4  = idx & 3;
            int grow = rowBase + r;
            float4 v = make_float4(0.f, 0.f, 0.f, 0.f);
            if (grow < M)
                v = *(const float4*)(A + (size_t)grow * K + k0 + c4 * 4);
            As[c4 * 4 + 0][r] = v.x;
            As[c4 * 4 + 1][r] = v.y;
            As[c4 * 4 + 2][r] = v.z;
            As[c4 * 4 + 3][r] = v.w;
        }
        {
            int r  = t >> 4;   // 0..15
            int c4 = t & 15;   // 0..15
            float4 v = *(const float4*)(W + (size_t)(k0 + r) * NC + c4 * 4);
            *(float4*)&Bs[r][c4 * 4] = v;
        }
        __syncthreads();
        #pragma unroll
        for (int k = 0; k < 16; k++) {
            float a[8], b[4];
            #pragma unroll
            for (int i = 0; i < 8; i++) a[i] = As[k][ty * 8 + i];
            #pragma unroll
            for (int j = 0; j < 4; j++) b[j] = Bs[k][tx * 4 + j];
            #pragma unroll
            for (int i = 0; i < 8; i++)
                #pragma unroll
                for (int j = 0; j < 4; j++)
                    acc[i][j] += a[i] * b[j];
        }
        __syncthreads();
    }
}

__global__ __launch_bounds__(256) void layer1_kernel(
    const float* __restrict__ Wm1, const float* __restrict__ bm1,
    const float* __restrict__ Wv1, const float* __restrict__ bv1,
    int M)
{
    __shared__ float As[16][128];
    __shared__ float Bs[16][64];
    int rowBase = blockIdx.x * 128;
    int t  = threadIdx.x;
    int tx = t & 15;
    int ty = t >> 4;

    float acc0[8][4], acc1[8][4];
    #pragma unroll
    for (int i = 0; i < 8; i++)
        #pragma unroll
        for (int j = 0; j < 4; j++) { acc0[i][j] = 0.f; acc1[i][j] = 0.f; }

    l1_mm_path(g_Hm, Wm1, rowBase, M, tx, ty, acc0, As, Bs);
    l1_mm_path(g_Hv, Wv1, rowBase, M, tx, ty, acc1, As, Bs);

    #pragma unroll
    for (int i = 0; i < 8; i++) {
        int r = rowBase + ty * 8 + i;
        if (r >= M) continue;
        float s0 = g_dis[r], s1 = g_di[r];
        float w0 = s0 * s0;        // self-loop weight for mean path
        float w1 = s1 * s1;        // self-loop weight for var path
        #pragma unroll
        for (int j = 0; j < 4; j++) {
            int c = tx * 4 + j;
            float mv = acc0[i][j] + bm1[c];
            mv = (mv > 0.0f) ? mv : expm1f(mv);                 // elu
            float vv = fmaxf(acc1[i][j] + bv1[c], 0.0f) + 1e-6f; // relu + eps
            float at = expf(-vv);
            float mo = mv * at;
            float vo = vv * at * at;
            size_t o = (size_t)r * CLS + c;
            g_m64[o]  = mo;
            g_v64[o]  = vo;
            g_accm[o] = w0 * mo;   // init with self-loop contribution
            g_accv[o] = w1 * vo;
        }
    }
}

// ---------------- SpMM over edges (warp per edge, fp32 RED atomics) ----------------
__global__ __launch_bounds__(256) void spmm_kernel(
    const int* __restrict__ src, const int* __restrict__ dst, int E)
{
    int e    = (blockIdx.x * 256 + threadIdx.x) >> 5;
    int lane = threadIdx.x & 31;
    if (e >= E) return;
    int s = __ldg(src + e);
    int d = __ldg(dst + e);
    float w0 = g_dis[s] * g_dis[d];
    float w1 = g_di[s]  * g_di[d];
    int f = lane * 2;
    float2 mm = *(const float2*)(g_m64 + (size_t)d * CLS + f);
    float2 vv = *(const float2*)(g_v64 + (size_t)d * CLS + f);
    float* am = g_accm + (size_t)s * CLS + f;
    float* av = g_accv + (size_t)s * CLS + f;
    atomicAdd(am,     w0 * mm.x);
    atomicAdd(am + 1, w0 * mm.y);
    atomicAdd(av,     w1 * vv.x);
    atomicAdd(av + 1, w1 * vv.y);
}

// ---------------- finalize: out = m + sample*sqrt(v); log_softmax --------------
__global__ __launch_bounds__(256) void finalize_kernel(
    const float* __restrict__ sample, float* __restrict__ out, int n)
{
    int w    = (blockIdx.x * 256 + threadIdx.x) >> 5;
    int lane = threadIdx.x & 31;
    if (w >= n) return;
    size_t base = (size_t)w * CLS;
    float va = g_accm[base + lane]      + sample[base + lane]      * sqrtf(fmaxf(g_accv[base + lane],      0.f));
    float vb = g_accm[base + 32 + lane] + sample[base + 32 + lane] * sqrtf(fmaxf(g_accv[base + 32 + lane], 0.f));
    float mx = fmaxf(va, vb);
    #pragma unroll
    for (int o = 16; o; o >>= 1) mx = fmaxf(mx, __shfl_xor_sync(0xFFFFFFFFu, mx, o));
    float sum = expf(va - mx) + expf(vb - mx);
    #pragma unroll
    for (int o = 16; o; o >>= 1) sum += __shfl_xor_sync(0xFFFFFFFFu, sum, o);
    float lse = mx + logf(sum);
    out[base + lane]      = va - lse;
    out[base + 32 + lane] = vb - lse;
}

// ---------------- launch ----------------
extern "C" void kernel_launch(void* const* d_in, const int* in_sizes, int n_in,
                              void* d_out, int out_size)
{
    const float* x      = (const float*)d_in[0];
    const float* Wm0    = (const float*)d_in[1];
    const float* bm0    = (const float*)d_in[2];
    const float* Wv0    = (const float*)d_in[3];
    const float* bv0    = (const float*)d_in[4];
    const float* Wm1    = (const float*)d_in[5];
    const float* bm1    = (const float*)d_in[6];
    const float* Wv1    = (const float*)d_in[7];
    const float* bv1    = (const float*)d_in[8];
    const float* sample = (const float*)d_in[9];
    const int*   esrc   = (const int*)d_in[10];
    const int*   edst   = (const int*)d_in[11];
    float* out = (float*)d_out;

    int M = in_sizes[0] / FIN;     // 100000
    int E = in_sizes[10];          // 3200000
    if (M > NNODE) M = NNODE;

    count_init_kernel <<<(M + 255) / 256, 256>>>(M);
    count_edges_kernel<<<(E + 255) / 256, 256>>>(esrc, E);
    make_deg_kernel   <<<(M + 255) / 256, 256>>>(M);

    dim3 g0(HID / BN, (M + BM - 1) / BM, 2);
    gemm0_kernel<<<g0, 256>>>(x, Wm0, bm0, Wv0, bv0, M);

    layer1_kernel<<<(M + 127) / 128, 256>>>(Wm1, bm1, Wv1, bv1, M);

    spmm_kernel<<<(E + 7) / 8, 256>>>(esrc, edst, E);

    finalize_kernel<<<((size_t)M * 32 + 255) / 256, 256>>>(sample, out, M);
}

// round 5
// speedup vs baseline: 1.7600x; 1.7600x over previous
#include <cuda_runtime.h>
#include <cuda_bf16.h>
#include <math.h>
#include <stdint.h>

#define NNODE 100000
#define FIN   512
#define HID   256
#define CLS   64

// ---------------- scratch (static device globals; no allocation) ----------------
__device__ float g_Hm[(size_t)NNODE * HID];   // elu(x@Wm0+bm0)
__device__ float g_Hv[(size_t)NNODE * HID];   // relu(x@Wv0+bv0)
__device__ float g_m64[(size_t)NNODE * CLS];  // mean*attn
__device__ float g_v64[(size_t)NNODE * CLS];  // var*attn^2
__device__ float g_accm[(size_t)NNODE * CLS]; // spmm accumulators
__device__ float g_accv[(size_t)NNODE * CLS];
__device__ int   g_cnt[NNODE];
__device__ float g_dis[NNODE];                // deg^-0.5
__device__ float g_di[NNODE];                 // deg^-1

// ---------------- degree ----------------
__global__ void count_init_kernel(int n) {
    int i = blockIdx.x * blockDim.x + threadIdx.x;
    if (i < n) g_cnt[i] = 1;   // self loop
}
__global__ void count_edges_kernel(const int* __restrict__ src, int e) {
    int i = blockIdx.x * blockDim.x + threadIdx.x;
    if (i < e) atomicAdd(&g_cnt[src[i]], 1);
}
__global__ void make_deg_kernel(int n) {
    int i = blockIdx.x * blockDim.x + threadIdx.x;
    if (i < n) {
        float c = (float)g_cnt[i];
        g_dis[i] = 1.0f / sqrtf(c);
        g_di[i]  = 1.0f / c;
    }
}

// ---------------- tf32 mma.sync helpers (legal at compute_103; no 'a'-gated ops) ----
__device__ __forceinline__ void mma_tf32(float* c, const uint32_t* a, const uint32_t* b) {
    asm volatile(
        "mma.sync.aligned.m16n8k8.row.col.f32.tf32.tf32.f32 "
        "{%0,%1,%2,%3}, {%4,%5,%6,%7}, {%8,%9}, {%0,%1,%2,%3};"
        : "+f"(c[0]), "+f"(c[1]), "+f"(c[2]), "+f"(c[3])
        : "r"(a[0]), "r"(a[1]), "r"(a[2]), "r"(a[3]), "r"(b[0]), "r"(b[1]));
}
__device__ __forceinline__ float4 cvt4_tf32(float4 v) {
    uint32_t x, y, z, w;
    asm("cvt.rna.tf32.f32 %0, %1;" : "=r"(x) : "f"(v.x));
    asm("cvt.rna.tf32.f32 %0, %1;" : "=r"(y) : "f"(v.y));
    asm("cvt.rna.tf32.f32 %0, %1;" : "=r"(z) : "f"(v.z));
    asm("cvt.rna.tf32.f32 %0, %1;" : "=r"(w) : "f"(v.w));
    return make_float4(__uint_as_float(x), __uint_as_float(y),
                       __uint_as_float(z), __uint_as_float(w));
}

// ---------------- layer-0 GEMM: H = act(X @ W + b) via tf32 HMMA -----------------
// BM=128, BN=128, BK=16, 256 thr (8 warps 2x4), warp tile 64x32, double-buffered.
// grid = (4, M/128): x = {nb(bit0), path(bit1)} so row-block sharers are wave-adjacent.
__global__ __launch_bounds__(256) void gemm0_mma_kernel(
    const float* __restrict__ X,
    const float* __restrict__ Wm, const float* __restrict__ bm,
    const float* __restrict__ Wv, const float* __restrict__ bv,
    int M)
{
    __shared__ __align__(16) float As[2][128][20];   // [m][k], stride 20 (conflict-free A frags)
    __shared__ __align__(16) float Bs[2][16][136];   // [k][n], stride 136 (conflict-free B frags)

    int nb   = blockIdx.x & 1;
    int path = blockIdx.x >> 1;
    const float* W    = path ? Wv : Wm;
    const float* bias = path ? bv : bm;
    float* H          = path ? g_Hv : g_Hm;

    int rowBase = blockIdx.y * 128;
    int t = threadIdx.x, wid = t >> 5, lane = t & 31;
    int warpM = wid >> 2, warpN = wid & 3;     // 2 x 4 warps
    int lr = lane >> 2, lc = lane & 3;         // fragment row/col ids

    float acc[4][4][4];
    #pragma unroll
    for (int i = 0; i < 4; i++)
        #pragma unroll
        for (int j = 0; j < 4; j++)
            #pragma unroll
            for (int q = 0; q < 4; q++) acc[i][j][q] = 0.0f;

    // ---- load tile 0 ----
    {
        #pragma unroll
        for (int l = 0; l < 2; l++) {
            int idx = t + l * 256;
            int m = idx >> 2, kq = idx & 3;
            int gr = rowBase + m;
            float4 v = make_float4(0.f, 0.f, 0.f, 0.f);
            if (gr < M) v = *(const float4*)(X + (size_t)gr * FIN + kq * 4);
            *(float4*)&As[0][m][kq * 4] = cvt4_tf32(v);
            int k2 = idx >> 5, nq = idx & 31;
            float4 w = *(const float4*)(W + (size_t)k2 * HID + nb * 128 + nq * 4);
            *(float4*)&Bs[0][k2][nq * 4] = cvt4_tf32(w);
        }
    }
    __syncthreads();

    for (int c = 0; c < 32; c++) {
        int cur = c & 1;
        float4 ar[2], br[2];
        if (c < 31) {
            int cn = c + 1;
            #pragma unroll
            for (int l = 0; l < 2; l++) {
                int idx = t + l * 256;
                int m = idx >> 2, kq = idx & 3;
                int gr = rowBase + m;
                ar[l] = make_float4(0.f, 0.f, 0.f, 0.f);
                if (gr < M) ar[l] = *(const float4*)(X + (size_t)gr * FIN + cn * 16 + kq * 4);
                int k2 = idx >> 5, nq = idx & 31;
                br[l] = *(const float4*)(W + (size_t)(cn * 16 + k2) * HID + nb * 128 + nq * 4);
            }
        }

        // ---- compute: 2 k-steps of 8 ----
        #pragma unroll
        for (int ks = 0; ks < 2; ks++) {
            int kb = ks * 8;
            uint32_t afr[4][4];
            #pragma unroll
            for (int mt = 0; mt < 4; mt++) {
                int m0 = warpM * 64 + mt * 16 + lr;
                afr[mt][0] = __float_as_uint(As[cur][m0][kb + lc]);
                afr[mt][1] = __float_as_uint(As[cur][m0 + 8][kb + lc]);
                afr[mt][2] = __float_as_uint(As[cur][m0][kb + lc + 4]);
                afr[mt][3] = __float_as_uint(As[cur][m0 + 8][kb + lc + 4]);
            }
            #pragma unroll
            for (int nt = 0; nt < 4; nt++) {
                int n0 = warpN * 32 + nt * 8 + lr;
                uint32_t bfr[2];
                bfr[0] = __float_as_uint(Bs[cur][kb + lc][n0]);
                bfr[1] = __float_as_uint(Bs[cur][kb + lc + 4][n0]);
                #pragma unroll
                for (int mt = 0; mt < 4; mt++) mma_tf32(acc[mt][nt], afr[mt], bfr);
            }
        }

        if (c < 31) {
            int nxt = (c + 1) & 1;
            #pragma unroll
            for (int l = 0; l < 2; l++) {
                int idx = t + l * 256;
                int m = idx >> 2, kq = idx & 3;
                *(float4*)&As[nxt][m][kq * 4] = cvt4_tf32(ar[l]);
                int k2 = idx >> 5, nq = idx & 31;
                *(float4*)&Bs[nxt][k2][nq * 4] = cvt4_tf32(br[l]);
            }
            __syncthreads();
        }
    }

    // ---- epilogue: bias + activation, fp32 store ----
    #pragma unroll
    for (int mt = 0; mt < 4; mt++) {
        int r0 = rowBase + warpM * 64 + mt * 16 + lr;
        #pragma unroll
        for (int nt = 0; nt < 4; nt++) {
            int cb = nb * 128 + warpN * 32 + nt * 8 + lc * 2;
            float b0 = bias[cb], b1 = bias[cb + 1];
            #pragma unroll
            for (int half = 0; half < 2; half++) {
                int r = r0 + half * 8;
                if (r >= M) continue;
                float v0 = acc[mt][nt][half * 2 + 0] + b0;
                float v1 = acc[mt][nt][half * 2 + 1] + b1;
                if (path == 0) {
                    v0 = (v0 > 0.0f) ? v0 : expm1f(v0);
                    v1 = (v1 > 0.0f) ? v1 : expm1f(v1);
                } else {
                    v0 = fmaxf(v0, 0.0f);
                    v1 = fmaxf(v1, 0.0f);
                }
                *(float2*)(H + (size_t)r * HID + cb) = make_float2(v0, v1);
            }
        }
    }
}

// ---------------- layer 1 fused: both paths + attn coupling + self-loop init ----
__device__ __forceinline__ void l1_mm_path(
    const float* __restrict__ A, const float* __restrict__ W,
    int rowBase, int M, int tx, int ty,
    float (&acc)[8][4], float (*As)[128], float (*Bs)[64])
{
    const int K = HID, NC = CLS;
    for (int k0 = 0; k0 < K; k0 += 16) {
        int t = ty * 16 + tx;
        #pragma unroll
        for (int l = 0; l < 2; l++) {
            int idx = t + l * 256;
            int r   = idx >> 2;
            int c4  = idx & 3;
            int grow = rowBase + r;
            float4 v = make_float4(0.f, 0.f, 0.f, 0.f);
            if (grow < M)
                v = *(const float4*)(A + (size_t)grow * K + k0 + c4 * 4);
            As[c4 * 4 + 0][r] = v.x;
            As[c4 * 4 + 1][r] = v.y;
            As[c4 * 4 + 2][r] = v.z;
            As[c4 * 4 + 3][r] = v.w;
        }
        {
            int r  = t >> 4;
            int c4 = t & 15;
            float4 v = *(const float4*)(W + (size_t)(k0 + r) * NC + c4 * 4);
            *(float4*)&Bs[r][c4 * 4] = v;
        }
        __syncthreads();
        #pragma unroll
        for (int k = 0; k < 16; k++) {
            float a[8], b[4];
            #pragma unroll
            for (int i = 0; i < 8; i++) a[i] = As[k][ty * 8 + i];
            #pragma unroll
            for (int j = 0; j < 4; j++) b[j] = Bs[k][tx * 4 + j];
            #pragma unroll
            for (int i = 0; i < 8; i++)
                #pragma unroll
                for (int j = 0; j < 4; j++)
                    acc[i][j] += a[i] * b[j];
        }
        __syncthreads();
    }
}

__global__ __launch_bounds__(256) void layer1_kernel(
    const float* __restrict__ Wm1, const float* __restrict__ bm1,
    const float* __restrict__ Wv1, const float* __restrict__ bv1,
    int M)
{
    __shared__ float As[16][128];
    __shared__ float Bs[16][64];
    int rowBase = blockIdx.x * 128;
    int t  = threadIdx.x;
    int tx = t & 15;
    int ty = t >> 4;

    float acc0[8][4], acc1[8][4];
    #pragma unroll
    for (int i = 0; i < 8; i++)
        #pragma unroll
        for (int j = 0; j < 4; j++) { acc0[i][j] = 0.f; acc1[i][j] = 0.f; }

    l1_mm_path(g_Hm, Wm1, rowBase, M, tx, ty, acc0, As, Bs);
    l1_mm_path(g_Hv, Wv1, rowBase, M, tx, ty, acc1, As, Bs);

    #pragma unroll
    for (int i = 0; i < 8; i++) {
        int r = rowBase + ty * 8 + i;
        if (r >= M) continue;
        float s0 = g_dis[r], s1 = g_di[r];
        float w0 = s0 * s0;        // self-loop weight, mean path
        float w1 = s1 * s1;        // self-loop weight, var path
        #pragma unroll
        for (int j = 0; j < 4; j++) {
            int c = tx * 4 + j;
            float mv = acc0[i][j] + bm1[c];
            mv = (mv > 0.0f) ? mv : expm1f(mv);                  // elu
            float vv = fmaxf(acc1[i][j] + bv1[c], 0.0f) + 1e-6f; // relu + eps
            float at = expf(-vv);
            float mo = mv * at;
            float vo = vv * at * at;
            size_t o = (size_t)r * CLS + c;
            g_m64[o]  = mo;
            g_v64[o]  = vo;
            g_accm[o] = w0 * mo;
            g_accv[o] = w1 * vo;
        }
    }
}

// ---------------- SpMM over edges (warp per edge, fp32 RED atomics) ------------
__global__ __launch_bounds__(256) void spmm_kernel(
    const int* __restrict__ src, const int* __restrict__ dst, int E)
{
    int e    = (blockIdx.x * 256 + threadIdx.x) >> 5;
    int lane = threadIdx.x & 31;
    if (e >= E) return;
    int s = __ldg(src + e);
    int d = __ldg(dst + e);
    float w0 = g_dis[s] * g_dis[d];
    float w1 = g_di[s]  * g_di[d];
    int f = lane * 2;
    float2 mm = *(const float2*)(g_m64 + (size_t)d * CLS + f);
    float2 vv = *(const float2*)(g_v64 + (size_t)d * CLS + f);
    float* am = g_accm + (size_t)s * CLS + f;
    float* av = g_accv + (size_t)s * CLS + f;
    atomicAdd(am,     w0 * mm.x);
    atomicAdd(am + 1, w0 * mm.y);
    atomicAdd(av,     w1 * vv.x);
    atomicAdd(av + 1, w1 * vv.y);
}

// ---------------- finalize: out = m + sample*sqrt(v); log_softmax --------------
__global__ __launch_bounds__(256) void finalize_kernel(
    const float* __restrict__ sample, float* __restrict__ out, int n)
{
    int w    = (blockIdx.x * 256 + threadIdx.x) >> 5;
    int lane = threadIdx.x & 31;
    if (w >= n) return;
    size_t base = (size_t)w * CLS;
    float va = g_accm[base + lane]      + sample[base + lane]      * sqrtf(fmaxf(g_accv[base + lane],      0.f));
    float vb = g_accm[base + 32 + lane] + sample[base + 32 + lane] * sqrtf(fmaxf(g_accv[base + 32 + lane], 0.f));
    float mx = fmaxf(va, vb);
    #pragma unroll
    for (int o = 16; o; o >>= 1) mx = fmaxf(mx, __shfl_xor_sync(0xFFFFFFFFu, mx, o));
    float sum = expf(va - mx) + expf(vb - mx);
    #pragma unroll
    for (int o = 16; o; o >>= 1) sum += __shfl_xor_sync(0xFFFFFFFFu, sum, o);
    float lse = mx + logf(sum);
    out[base + lane]      = va - lse;
    out[base + 32 + lane] = vb - lse;
}

// ---------------- launch ----------------
extern "C" void kernel_launch(void* const* d_in, const int* in_sizes, int n_in,
                              void* d_out, int out_size)
{
    const float* x      = (const float*)d_in[0];
    const float* Wm0    = (const float*)d_in[1];
    const float* bm0    = (const float*)d_in[2];
    const float* Wv0    = (const float*)d_in[3];
    const float* bv0    = (const float*)d_in[4];
    const float* Wm1    = (const float*)d_in[5];
    const float* bm1    = (const float*)d_in[6];
    const float* Wv1    = (const float*)d_in[7];
    const float* bv1    = (const float*)d_in[8];
    const float* sample = (const float*)d_in[9];
    const int*   esrc   = (const int*)d_in[10];
    const int*   edst   = (const int*)d_in[11];
    float* out = (float*)d_out;

    int M = in_sizes[0] / FIN;     // 100000
    int E = in_sizes[10];          // 3200000
    if (M > NNODE) M = NNODE;

    count_init_kernel <<<(M + 255) / 256, 256>>>(M);
    count_edges_kernel<<<(E + 255) / 256, 256>>>(esrc, E);
    make_deg_kernel   <<<(M + 255) / 256, 256>>>(M);

    dim3 g0(4, (M + 127) / 128);   // x: {nb, path}; row-block sharers adjacent for L2
    gemm0_mma_kernel<<<g0, 256>>>(x, Wm0, bm0, Wv0, bv0, M);

    layer1_kernel<<<(M + 127) / 128, 256>>>(Wm1, bm1, Wv1, bv1, M);

    spmm_kernel<<<(E + 7) / 8, 256>>>(esrc, edst, E);

    finalize_kernel<<<((size_t)M * 32 + 255) / 256, 256>>>(sample, out, M);
}

// round 7
// speedup vs baseline: 2.7334x; 1.5530x over previous
#include <cuda_runtime.h>
#include <cuda_bf16.h>
#include <math.h>
#include <stdint.h>

#define NNODE 100000
#define MAXE  3400000
#define FIN   512
#define HID   256
#define CLS   64

// ---------------- scratch (static device globals; no allocation) ----------------
__device__ float g_Hm[(size_t)NNODE * HID];   // elu(x@Wm0+bm0)
__device__ float g_Hv[(size_t)NNODE * HID];   // relu(x@Wv0+bv0)
__device__ float g_m64[(size_t)NNODE * CLS];  // mean*attn
__device__ float g_v64[(size_t)NNODE * CLS];  // var*attn^2
__device__ int   g_ecnt[NNODE];               // out-degree (no self loop)
__device__ int   g_rowstart[NNODE];           // CSR row starts
__device__ int   g_fill[NNODE];               // scatter cursors
__device__ int   g_bsums[128];                // scan block sums
__device__ int   g_eidx[MAXE];                // CSR dst indices
__device__ float g_dis[NNODE];                // deg^-0.5
__device__ float g_di[NNODE];                 // deg^-1

// ---------------- degree + CSR build ----------------
__global__ void zero_ecnt_kernel(int n) {
    int i = blockIdx.x * blockDim.x + threadIdx.x;
    if (i < n) g_ecnt[i] = 0;
}
__global__ void count_edges_kernel(const int* __restrict__ src, int e) {
    int i = blockIdx.x * blockDim.x + threadIdx.x;
    if (i < e) atomicAdd(&g_ecnt[src[i]], 1);
}
__global__ void make_deg_kernel(int n) {
    int i = blockIdx.x * blockDim.x + threadIdx.x;
    if (i < n) {
        float c = (float)(g_ecnt[i] + 1);   // + self loop
        g_dis[i] = 1.0f / sqrtf(c);
        g_di[i]  = 1.0f / c;
    }
}
// block-wise exclusive scan of g_ecnt -> g_rowstart (within-block) + block sums
__global__ __launch_bounds__(1024) void scan_blocks_kernel(int n) {
    __shared__ int sh[1024];
    int tid = threadIdx.x;
    int gid = blockIdx.x * 1024 + tid;
    int v = (gid < n) ? g_ecnt[gid] : 0;
    sh[tid] = v;
    __syncthreads();
    for (int off = 1; off < 1024; off <<= 1) {
        int t = (tid >= off) ? sh[tid - off] : 0;
        __syncthreads();
        sh[tid] += t;
        __syncthreads();
    }
    if (gid < n) g_rowstart[gid] = sh[tid] - v;   // exclusive
    if (tid == 1023) g_bsums[blockIdx.x] = sh[1023];
}
__global__ void scan_tops_kernel(int nblk) {
    __shared__ int sh[128];
    int tid = threadIdx.x;
    int v = (tid < nblk) ? g_bsums[tid] : 0;
    sh[tid] = v;
    __syncthreads();
    for (int off = 1; off < 128; off <<= 1) {
        int t = (tid >= off) ? sh[tid - off] : 0;
        __syncthreads();
        sh[tid] += t;
        __syncthreads();
    }
    if (tid < nblk) g_bsums[tid] = sh[tid] - v;   // exclusive
}
__global__ void scan_add_kernel(int n) {
    int i = blockIdx.x * blockDim.x + threadIdx.x;
    if (i < n) {
        int rs = g_rowstart[i] + g_bsums[i >> 10];
        g_rowstart[i] = rs;
        g_fill[i] = rs;
    }
}
__global__ void scatter_edges_kernel(const int* __restrict__ src,
                                     const int* __restrict__ dst, int e) {
    int i = blockIdx.x * blockDim.x + threadIdx.x;
    if (i < e) {
        int pos = atomicAdd(&g_fill[src[i]], 1);
        g_eidx[pos] = dst[i];
    }
}

// ---------------- tf32 mma.sync helpers (legal at compute_103) ----------------
__device__ __forceinline__ void mma_tf32(float* c, const uint32_t* a, const uint32_t* b) {
    asm volatile(
        "mma.sync.aligned.m16n8k8.row.col.f32.tf32.tf32.f32 "
        "{%0,%1,%2,%3}, {%4,%5,%6,%7}, {%8,%9}, {%0,%1,%2,%3};"
        : "+f"(c[0]), "+f"(c[1]), "+f"(c[2]), "+f"(c[3])
        : "r"(a[0]), "r"(a[1]), "r"(a[2]), "r"(a[3]), "r"(b[0]), "r"(b[1]));
}
__device__ __forceinline__ float4 cvt4_tf32(float4 v) {
    uint32_t x, y, z, w;
    asm("cvt.rna.tf32.f32 %0, %1;" : "=r"(x) : "f"(v.x));
    asm("cvt.rna.tf32.f32 %0, %1;" : "=r"(y) : "f"(v.y));
    asm("cvt.rna.tf32.f32 %0, %1;" : "=r"(z) : "f"(v.z));
    asm("cvt.rna.tf32.f32 %0, %1;" : "=r"(w) : "f"(v.w));
    return make_float4(__uint_as_float(x), __uint_as_float(y),
                       __uint_as_float(z), __uint_as_float(w));
}

// ---------------- layer-0 GEMM: H = act(X @ W + b) via tf32 HMMA -----------------
__global__ __launch_bounds__(256) void gemm0_mma_kernel(
    const float* __restrict__ X,
    const float* __restrict__ Wm, const float* __restrict__ bm,
    const float* __restrict__ Wv, const float* __restrict__ bv,
    int M)
{
    __shared__ __align__(16) float As[2][128][20];
    __shared__ __align__(16) float Bs[2][16][136];

    int nb   = blockIdx.x & 1;
    int path = blockIdx.x >> 1;
    const float* W    = path ? Wv : Wm;
    const float* bias = path ? bv : bm;
    float* H          = path ? g_Hv : g_Hm;

    int rowBase = blockIdx.y * 128;
    int t = threadIdx.x, wid = t >> 5, lane = t & 31;
    int warpM = wid >> 2, warpN = wid & 3;
    int lr = lane >> 2, lc = lane & 3;

    float acc[4][4][4];
    #pragma unroll
    for (int i = 0; i < 4; i++)
        #pragma unroll
        for (int j = 0; j < 4; j++)
            #pragma unroll
            for (int q = 0; q < 4; q++) acc[i][j][q] = 0.0f;

    {
        #pragma unroll
        for (int l = 0; l < 2; l++) {
            int idx = t + l * 256;
            int m = idx >> 2, kq = idx & 3;
            int gr = rowBase + m;
            float4 v = make_float4(0.f, 0.f, 0.f, 0.f);
            if (gr < M) v = *(const float4*)(X + (size_t)gr * FIN + kq * 4);
            *(float4*)&As[0][m][kq * 4] = cvt4_tf32(v);
            int k2 = idx >> 5, nq = idx & 31;
            float4 w = *(const float4*)(W + (size_t)k2 * HID + nb * 128 + nq * 4);
            *(float4*)&Bs[0][k2][nq * 4] = cvt4_tf32(w);
        }
    }
    __syncthreads();

    for (int c = 0; c < 32; c++) {
        int cur = c & 1;
        float4 ar[2], br[2];
        if (c < 31) {
            int cn = c + 1;
            #pragma unroll
            for (int l = 0; l < 2; l++) {
                int idx = t + l * 256;
                int m = idx >> 2, kq = idx & 3;
                int gr = rowBase + m;
                ar[l] = make_float4(0.f, 0.f, 0.f, 0.f);
                if (gr < M) ar[l] = *(const float4*)(X + (size_t)gr * FIN + cn * 16 + kq * 4);
                int k2 = idx >> 5, nq = idx & 31;
                br[l] = *(const float4*)(W + (size_t)(cn * 16 + k2) * HID + nb * 128 + nq * 4);
            }
        }

        #pragma unroll
        for (int ks = 0; ks < 2; ks++) {
            int kb = ks * 8;
            uint32_t afr[4][4];
            #pragma unroll
            for (int mt = 0; mt < 4; mt++) {
                int m0 = warpM * 64 + mt * 16 + lr;
                afr[mt][0] = __float_as_uint(As[cur][m0][kb + lc]);
                afr[mt][1] = __float_as_uint(As[cur][m0 + 8][kb + lc]);
                afr[mt][2] = __float_as_uint(As[cur][m0][kb + lc + 4]);
                afr[mt][3] = __float_as_uint(As[cur][m0 + 8][kb + lc + 4]);
            }
            #pragma unroll
            for (int nt = 0; nt < 4; nt++) {
                int n0 = warpN * 32 + nt * 8 + lr;
                uint32_t bfr[2];
                bfr[0] = __float_as_uint(Bs[cur][kb + lc][n0]);
                bfr[1] = __float_as_uint(Bs[cur][kb + lc + 4][n0]);
                #pragma unroll
                for (int mt = 0; mt < 4; mt++) mma_tf32(acc[mt][nt], afr[mt], bfr);
            }
        }

        if (c < 31) {
            int nxt = (c + 1) & 1;
            #pragma unroll
            for (int l = 0; l < 2; l++) {
                int idx = t + l * 256;
                int m = idx >> 2, kq = idx & 3;
                *(float4*)&As[nxt][m][kq * 4] = cvt4_tf32(ar[l]);
                int k2 = idx >> 5, nq = idx & 31;
                *(float4*)&Bs[nxt][k2][nq * 4] = cvt4_tf32(br[l]);
            }
            __syncthreads();
        }
    }

    #pragma unroll
    for (int mt = 0; mt < 4; mt++) {
        int r0 = rowBase + warpM * 64 + mt * 16 + lr;
        #pragma unroll
        for (int nt = 0; nt < 4; nt++) {
            int cb = nb * 128 + warpN * 32 + nt * 8 + lc * 2;
            float b0 = bias[cb], b1 = bias[cb + 1];
            #pragma unroll
            for (int half = 0; half < 2; half++) {
                int r = r0 + half * 8;
                if (r >= M) continue;
                float v0 = acc[mt][nt][half * 2 + 0] + b0;
                float v1 = acc[mt][nt][half * 2 + 1] + b1;
                if (path == 0) {
                    v0 = (v0 > 0.0f) ? v0 : expm1f(v0);
                    v1 = (v1 > 0.0f) ? v1 : expm1f(v1);
                } else {
                    v0 = fmaxf(v0, 0.0f);
                    v1 = fmaxf(v1, 0.0f);
                }
                *(float2*)(H + (size_t)r * HID + cb) = make_float2(v0, v1);
            }
        }
    }
}

// ---------------- layer-1 via tf32 HMMA: both paths + attn coupling --------------
// BM=128, BN=64, K=256. 8 warps (2 warpM x 4 warpN), warp tile 64x16.
__global__ __launch_bounds__(256) void layer1_mma_kernel(
    const float* __restrict__ Wm1, const float* __restrict__ bm1,
    const float* __restrict__ Wv1, const float* __restrict__ bv1,
    int M)
{
    __shared__ __align__(16) float As[2][128][20];
    __shared__ __align__(16) float Bs[2][16][72];

    int rowBase = blockIdx.x * 128;
    int t = threadIdx.x, wid = t >> 5, lane = t & 31;
    int warpM = wid >> 2, warpN = wid & 3;
    int lr = lane >> 2, lc = lane & 3;

    float acc[2][4][2][4];
    #pragma unroll
    for (int p = 0; p < 2; p++)
        #pragma unroll
        for (int i = 0; i < 4; i++)
            #pragma unroll
            for (int j = 0; j < 2; j++)
                #pragma unroll
                for (int q = 0; q < 4; q++) acc[p][i][j][q] = 0.0f;

    #pragma unroll
    for (int p = 0; p < 2; p++) {
        const float* A = p ? g_Hv : g_Hm;
        const float* W = p ? Wv1 : Wm1;
        __syncthreads();
        // preload chunk 0
        {
            #pragma unroll
            for (int l = 0; l < 2; l++) {
                int idx = t + l * 256;
                int m = idx >> 2, kq = idx & 3;
                int gr = rowBase + m;
                float4 v = make_float4(0.f, 0.f, 0.f, 0.f);
                if (gr < M) v = *(const float4*)(A + (size_t)gr * HID + kq * 4);
                *(float4*)&As[0][m][kq * 4] = cvt4_tf32(v);
            }
            int k2 = t >> 4, nq = t & 15;
            float4 w = *(const float4*)(W + (size_t)k2 * CLS + nq * 4);
            *(float4*)&Bs[0][k2][nq * 4] = cvt4_tf32(w);
        }
        __syncthreads();

        for (int c = 0; c < 16; c++) {
            int cur = c & 1;
            float4 ar[2], br;
            if (c < 15) {
                int cn = c + 1;
                #pragma unroll
                for (int l = 0; l < 2; l++) {
                    int idx = t + l * 256;
                    int m = idx >> 2, kq = idx & 3;
                    int gr = rowBase + m;
                    ar[l] = make_float4(0.f, 0.f, 0.f, 0.f);
                    if (gr < M) ar[l] = *(const float4*)(A + (size_t)gr * HID + cn * 16 + kq * 4);
                }
                int k2 = t >> 4, nq = t & 15;
                br = *(const float4*)(W + (size_t)(c * 16 + 16 + k2) * CLS + nq * 4);
            }

            #pragma unroll
            for (int ks = 0; ks < 2; ks++) {
                int kb = ks * 8;
                uint32_t afr[4][4];
                #pragma unroll
                for (int mt = 0; mt < 4; mt++) {
                    int m0 = warpM * 64 + mt * 16 + lr;
                    afr[mt][0] = __float_as_uint(As[cur][m0][kb + lc]);
                    afr[mt][1] = __float_as_uint(As[cur][m0 + 8][kb + lc]);
                    afr[mt][2] = __float_as_uint(As[cur][m0][kb + lc + 4]);
                    afr[mt][3] = __float_as_uint(As[cur][m0 + 8][kb + lc + 4]);
                }
                #pragma unroll
                for (int nt = 0; nt < 2; nt++) {
                    int n0 = warpN * 16 + nt * 8 + lr;
                    uint32_t bfr[2];
                    bfr[0] = __float_as_uint(Bs[cur][kb + lc][n0]);
                    bfr[1] = __float_as_uint(Bs[cur][kb + lc + 4][n0]);
                    #pragma unroll
                    for (int mt = 0; mt < 4; mt++) mma_tf32(acc[p][mt][nt], afr[mt], bfr);
                }
            }

            if (c < 15) {
                int nxt = (c + 1) & 1;
                #pragma unroll
                for (int l = 0; l < 2; l++) {
                    int idx = t + l * 256;
                    int m = idx >> 2, kq = idx & 3;
                    *(float4*)&As[nxt][m][kq * 4] = cvt4_tf32(ar[l]);
                }
                int k2 = t >> 4, nq = t & 15;
                *(float4*)&Bs[nxt][k2][nq * 4] = cvt4_tf32(br);
                __syncthreads();
            }
        }
    }

    // fused epilogue: elu/relu + attn coupling, write m64/v64
    #pragma unroll
    for (int mt = 0; mt < 4; mt++) {
        int r0 = rowBase + warpM * 64 + mt * 16 + lr;
        #pragma unroll
        for (int nt = 0; nt < 2; nt++) {
            int cb = warpN * 16 + nt * 8 + lc * 2;
            float bm0c = bm1[cb], bm1c = bm1[cb + 1];
            float bv0c = bv1[cb], bv1c = bv1[cb + 1];
            #pragma unroll
            for (int half = 0; half < 2; half++) {
                int r = r0 + half * 8;
                if (r >= M) continue;
                float m0 = acc[0][mt][nt][half * 2 + 0] + bm0c;
                float m1 = acc[0][mt][nt][half * 2 + 1] + bm1c;
                m0 = (m0 > 0.0f) ? m0 : expm1f(m0);
                m1 = (m1 > 0.0f) ? m1 : expm1f(m1);
                float v0 = fmaxf(acc[1][mt][nt][half * 2 + 0] + bv0c, 0.0f) + 1e-6f;
                float v1 = fmaxf(acc[1][mt][nt][half * 2 + 1] + bv1c, 0.0f) + 1e-6f;
                float a0 = expf(-v0), a1 = expf(-v1);
                size_t o = (size_t)r * CLS + cb;
                *(float2*)(g_m64 + o) = make_float2(m0 * a0, m1 * a1);
                *(float2*)(g_v64 + o) = make_float2(v0 * a0 * a0, v1 * a1 * a1);
            }
        }
    }
}

// ---------------- fused SpMM (CSR, no atomics) + finalize ----------------------
__global__ __launch_bounds__(256) void spmm_fused_kernel(
    const float* __restrict__ sample, float* __restrict__ out, int n)
{
    int s    = (blockIdx.x * 256 + threadIdx.x) >> 5;
    int lane = threadIdx.x & 31;
    if (s >= n) return;

    float dis_s = g_dis[s], di_s = g_di[s];
    int start = g_rowstart[s];
    int cnt   = g_ecnt[s];
    size_t base = (size_t)s * CLS;

    // self-loop contribution
    float am0 = dis_s * dis_s * g_m64[base + lane];
    float am1 = dis_s * dis_s * g_m64[base + 32 + lane];
    float av0 = di_s * di_s * g_v64[base + lane];
    float av1 = di_s * di_s * g_v64[base + 32 + lane];

    int j = 0;
    for (; j + 4 <= cnt; j += 4) {
        int d0 = g_eidx[start + j];
        int d1 = g_eidx[start + j + 1];
        int d2 = g_eidx[start + j + 2];
        int d3 = g_eidx[start + j + 3];
        float wm0 = dis_s * g_dis[d0], wv0 = di_s * g_di[d0];
        float wm1 = dis_s * g_dis[d1], wv1 = di_s * g_di[d1];
        float wm2 = dis_s * g_dis[d2], wv2 = di_s * g_di[d2];
        float wm3 = dis_s * g_dis[d3], wv3 = di_s * g_di[d3];
        size_t b0 = (size_t)d0 * CLS, b1 = (size_t)d1 * CLS;
        size_t b2 = (size_t)d2 * CLS, b3 = (size_t)d3 * CLS;
        am0 += wm0 * g_m64[b0 + lane]      + wm1 * g_m64[b1 + lane]
             + wm2 * g_m64[b2 + lane]      + wm3 * g_m64[b3 + lane];
        am1 += wm0 * g_m64[b0 + 32 + lane] + wm1 * g_m64[b1 + 32 + lane]
             + wm2 * g_m64[b2 + 32 + lane] + wm3 * g_m64[b3 + 32 + lane];
        av0 += wv0 * g_v64[b0 + lane]      + wv1 * g_v64[b1 + lane]
             + wv2 * g_v64[b2 + lane]      + wv3 * g_v64[b3 + lane];
        av1 += wv0 * g_v64[b0 + 32 + lane] + wv1 * g_v64[b1 + 32 + lane]
             + wv2 * g_v64[b2 + 32 + lane] + wv3 * g_v64[b3 + 32 + lane];
    }
    for (; j < cnt; j++) {
        int d = g_eidx[start + j];
        float wm = dis_s * g_dis[d], wv = di_s * g_di[d];
        size_t b = (size_t)d * CLS;
        am0 += wm * g_m64[b + lane];
        am1 += wm * g_m64[b + 32 + lane];
        av0 += wv * g_v64[b + lane];
        av1 += wv * g_v64[b + 32 + lane];
    }

    // finalize: out = m + sample*sqrt(v); log_softmax over 64
    float va = am0 + sample[base + lane]      * sqrtf(fmaxf(av0, 0.f));
    float vb = am1 + sample[base + 32 + lane] * sqrtf(fmaxf(av1, 0.f));
    float mx = fmaxf(va, vb);
    #pragma unroll
    for (int o = 16; o; o >>= 1) mx = fmaxf(mx, __shfl_xor_sync(0xFFFFFFFFu, mx, o));
    float sum = expf(va - mx) + expf(vb - mx);
    #pragma unroll
    for (int o = 16; o; o >>= 1) sum += __shfl_xor_sync(0xFFFFFFFFu, sum, o);
    float lse = mx + logf(sum);
    out[base + lane]      = va - lse;
    out[base + 32 + lane] = vb - lse;
}

// ---------------- launch ----------------
extern "C" void kernel_launch(void* const* d_in, const int* in_sizes, int n_in,
                              void* d_out, int out_size)
{
    const float* x      = (const float*)d_in[0];
    const float* Wm0    = (const float*)d_in[1];
    const float* bm0    = (const float*)d_in[2];
    const float* Wv0    = (const float*)d_in[3];
    const float* bv0    = (const float*)d_in[4];
    const float* Wm1    = (const float*)d_in[5];
    const float* bm1    = (const float*)d_in[6];
    const float* Wv1    = (const float*)d_in[7];
    const float* bv1    = (const float*)d_in[8];
    const float* sample = (const float*)d_in[9];
    const int*   esrc   = (const int*)d_in[10];
    const int*   edst   = (const int*)d_in[11];
    float* out = (float*)d_out;

    int M = in_sizes[0] / FIN;     // 100000
    int E = in_sizes[10];          // 3200000
    if (M > NNODE) M = NNODE;
    if (E > MAXE)  E = MAXE;
    int nblk = (M + 1023) / 1024;

    // degree + CSR build
    zero_ecnt_kernel    <<<(M + 255) / 256, 256>>>(M);
    count_edges_kernel  <<<(E + 255) / 256, 256>>>(esrc, E);
    make_deg_kernel     <<<(M + 255) / 256, 256>>>(M);
    scan_blocks_kernel  <<<nblk, 1024>>>(M);
    scan_tops_kernel    <<<1, 128>>>(nblk);
    scan_add_kernel     <<<(M + 255) / 256, 256>>>(M);
    scatter_edges_kernel<<<(E + 255) / 256, 256>>>(esrc, edst, E);

    // dense pipeline
    dim3 g0(4, (M + 127) / 128);
    gemm0_mma_kernel<<<g0, 256>>>(x, Wm0, bm0, Wv0, bv0, M);
    layer1_mma_kernel<<<(M + 127) / 128, 256>>>(Wm1, bm1, Wv1, bv1, M);

    // graph aggregation + output
    spmm_fused_kernel<<<((size_t)M * 32 + 255) / 256, 256>>>(sample, out, M);
}

// round 8
// speedup vs baseline: 3.2332x; 1.1828x over previous
#include <cuda_runtime.h>
#include <cuda_bf16.h>
#include <math.h>
#include <stdint.h>

#define NNODE 100000
#define MAXE  3400000
#define FIN   512
#define HID   256
#define CLS   64

// ---------------- scratch (static device globals; no allocation) ----------------
__device__ float g_Hm[(size_t)NNODE * HID];   // elu(x@Wm0+bm0)
__device__ float g_Hv[(size_t)NNODE * HID];   // relu(x@Wv0+bv0)
__device__ float g_m64[(size_t)NNODE * CLS];  // mean*attn
__device__ float g_v64[(size_t)NNODE * CLS];  // var*attn^2
__device__ int   g_ecnt[NNODE];               // out-degree (no self loop)
__device__ int   g_rowstart[NNODE];           // CSR row starts
__device__ int   g_fill[NNODE];               // scatter cursors
__device__ int   g_bsums[128];                // scan block sums
__device__ int   g_eidx[MAXE];                // CSR dst indices
__device__ float g_dis[NNODE];                // deg^-0.5
__device__ float g_di[NNODE];                 // deg^-1

// ---------------- degree + CSR build ----------------
__global__ void zero_ecnt_kernel(int n) {
    int i = blockIdx.x * blockDim.x + threadIdx.x;
    if (i < n) g_ecnt[i] = 0;
}
__global__ void count_edges_kernel(const int* __restrict__ src, int e) {
    int i = blockIdx.x * blockDim.x + threadIdx.x;
    if (i < e) atomicAdd(&g_ecnt[src[i]], 1);
}
__global__ void make_deg_kernel(int n) {
    int i = blockIdx.x * blockDim.x + threadIdx.x;
    if (i < n) {
        float c = (float)(g_ecnt[i] + 1);   // + self loop
        g_dis[i] = 1.0f / sqrtf(c);
        g_di[i]  = 1.0f / c;
    }
}
__global__ __launch_bounds__(1024) void scan_blocks_kernel(int n) {
    __shared__ int sh[1024];
    int tid = threadIdx.x;
    int gid = blockIdx.x * 1024 + tid;
    int v = (gid < n) ? g_ecnt[gid] : 0;
    sh[tid] = v;
    __syncthreads();
    for (int off = 1; off < 1024; off <<= 1) {
        int t = (tid >= off) ? sh[tid - off] : 0;
        __syncthreads();
        sh[tid] += t;
        __syncthreads();
    }
    if (gid < n) g_rowstart[gid] = sh[tid] - v;   // exclusive
    if (tid == 1023) g_bsums[blockIdx.x] = sh[1023];
}
__global__ void scan_tops_kernel(int nblk) {
    __shared__ int sh[128];
    int tid = threadIdx.x;
    int v = (tid < nblk) ? g_bsums[tid] : 0;
    sh[tid] = v;
    __syncthreads();
    for (int off = 1; off < 128; off <<= 1) {
        int t = (tid >= off) ? sh[tid - off] : 0;
        __syncthreads();
        sh[tid] += t;
        __syncthreads();
    }
    if (tid < nblk) g_bsums[tid] = sh[tid] - v;   // exclusive
}
__global__ void scan_add_kernel(int n) {
    int i = blockIdx.x * blockDim.x + threadIdx.x;
    if (i < n) {
        int rs = g_rowstart[i] + g_bsums[i >> 10];
        g_rowstart[i] = rs;
        g_fill[i] = rs;
    }
}
__global__ void scatter_edges_kernel(const int* __restrict__ src,
                                     const int* __restrict__ dst, int e) {
    int i = blockIdx.x * blockDim.x + threadIdx.x;
    if (i < e) {
        int pos = atomicAdd(&g_fill[src[i]], 1);
        g_eidx[pos] = dst[i];
    }
}

// ---------------- mma.sync + cp.async helpers (legal at compute_103) ------------
__device__ __forceinline__ void mma_tf32(float* c, const uint32_t* a, const uint32_t* b) {
    asm volatile(
        "mma.sync.aligned.m16n8k8.row.col.f32.tf32.tf32.f32 "
        "{%0,%1,%2,%3}, {%4,%5,%6,%7}, {%8,%9}, {%0,%1,%2,%3};"
        : "+f"(c[0]), "+f"(c[1]), "+f"(c[2]), "+f"(c[3])
        : "r"(a[0]), "r"(a[1]), "r"(a[2]), "r"(a[3]), "r"(b[0]), "r"(b[1]));
}
__device__ __forceinline__ uint32_t smem_u32(const void* p) {
    uint32_t a;
    asm("{ .reg .u64 t; cvta.to.shared.u64 t, %1; cvt.u32.u64 %0, t; }" : "=r"(a) : "l"(p));
    return a;
}
__device__ __forceinline__ void cp_async16(uint32_t dst, const void* src, int srcsize) {
    asm volatile("cp.async.cg.shared.global [%0], [%1], 16, %2;"
                 :: "r"(dst), "l"(src), "r"(srcsize) : "memory");
}
__device__ __forceinline__ void cp_commit() {
    asm volatile("cp.async.commit_group;" ::: "memory");
}
__device__ __forceinline__ void cp_wait1() {
    asm volatile("cp.async.wait_group 1;" ::: "memory");
}
__device__ __forceinline__ void cp_wait0() {
    asm volatile("cp.async.wait_group 0;" ::: "memory");
}

// ---------------- layer-0 GEMM: H = act(X @ W + b), cp.async 3-stage -------------
// BM=128, BN=128, BK=16, 256 thr (8 warps 2x4), warp tile 64x32.
// Stage layout (floats): A[128][20] then B[16][136]; 4736 floats/stage, 3 stages.
#define G0_ASTR 20
#define G0_BSTR 136
#define G0_STAGE (128 * G0_ASTR + 16 * G0_BSTR)   // 4736 floats
#define G0_SMEM  (3 * G0_STAGE * 4)               // 56832 bytes

__global__ __launch_bounds__(256) void gemm0_mma_kernel(
    const float* __restrict__ X,
    const float* __restrict__ Wm, const float* __restrict__ bm,
    const float* __restrict__ Wv, const float* __restrict__ bv,
    int M)
{
    extern __shared__ float smem[];

    int nb   = blockIdx.x & 1;
    int path = blockIdx.x >> 1;
    const float* W    = path ? Wv : Wm;
    const float* bias = path ? bv : bm;
    float* H          = path ? g_Hv : g_Hm;

    int rowBase = blockIdx.y * 128;
    int t = threadIdx.x, wid = t >> 5, lane = t & 31;
    int warpM = wid >> 2, warpN = wid & 3;
    int lr = lane >> 2, lc = lane & 3;

    // per-thread load coords
    int mA0 = t >> 2,        kqA = t & 3;          // A elem 0 (l=0)
    int mA1 = (t + 256) >> 2;                      // A elem 1 (l=1), same kq
    int k2B0 = t >> 5,       nqB = t & 31;         // B elem 0
    int k2B1 = (t + 256) >> 5;                     // B elem 1
    int szA0 = (rowBase + mA0 < M) ? 16 : 0;
    int szA1 = (rowBase + mA1 < M) ? 16 : 0;
    const float* XA0 = X + (size_t)(rowBase + mA0) * FIN + kqA * 4;
    const float* XA1 = X + (size_t)(rowBase + mA1) * FIN + kqA * 4;
    const float* WB0 = W + (size_t)k2B0 * HID + nb * 128 + nqB * 4;
    const float* WB1 = W + (size_t)k2B1 * HID + nb * 128 + nqB * 4;
    uint32_t dA0 = smem_u32(&smem[mA0 * G0_ASTR + kqA * 4]);
    uint32_t dA1 = smem_u32(&smem[mA1 * G0_ASTR + kqA * 4]);
    uint32_t dB0 = smem_u32(&smem[128 * G0_ASTR + k2B0 * G0_BSTR + nqB * 4]);
    uint32_t dB1 = smem_u32(&smem[128 * G0_ASTR + k2B1 * G0_BSTR + nqB * 4]);

    float acc[4][4][4];
    #pragma unroll
    for (int i = 0; i < 4; i++)
        #pragma unroll
        for (int j = 0; j < 4; j++)
            #pragma unroll
            for (int q = 0; q < 4; q++) acc[i][j][q] = 0.0f;

    // prologue: stages 0,1
    #pragma unroll
    for (int pc = 0; pc < 2; pc++) {
        uint32_t so = pc * G0_STAGE * 4;
        cp_async16(dA0 + so, XA0 + pc * 16, szA0);
        cp_async16(dA1 + so, XA1 + pc * 16, szA1);
        cp_async16(dB0 + so, WB0 + (size_t)pc * 16 * HID, 16);
        cp_async16(dB1 + so, WB1 + (size_t)pc * 16 * HID, 16);
        cp_commit();
    }

    for (int c = 0; c < 32; c++) {
        if (c < 30) cp_wait1(); else cp_wait0();
        __syncthreads();

        int cur = c - (c / 3) * 3;   // c % 3
        const float* sA = smem + cur * G0_STAGE;
        const float* sB = sA + 128 * G0_ASTR;

        #pragma unroll
        for (int ks = 0; ks < 2; ks++) {
            int kb = ks * 8;
            uint32_t afr[4][4];
            #pragma unroll
            for (int mt = 0; mt < 4; mt++) {
                int m0 = warpM * 64 + mt * 16 + lr;
                afr[mt][0] = __float_as_uint(sA[m0 * G0_ASTR + kb + lc]);
                afr[mt][1] = __float_as_uint(sA[(m0 + 8) * G0_ASTR + kb + lc]);
                afr[mt][2] = __float_as_uint(sA[m0 * G0_ASTR + kb + lc + 4]);
                afr[mt][3] = __float_as_uint(sA[(m0 + 8) * G0_ASTR + kb + lc + 4]);
            }
            #pragma unroll
            for (int nt = 0; nt < 4; nt++) {
                int n0 = warpN * 32 + nt * 8 + lr;
                uint32_t bfr[2];
                bfr[0] = __float_as_uint(sB[(kb + lc) * G0_BSTR + n0]);
                bfr[1] = __float_as_uint(sB[(kb + lc + 4) * G0_BSTR + n0]);
                #pragma unroll
                for (int mt = 0; mt < 4; mt++) mma_tf32(acc[mt][nt], afr[mt], bfr);
            }
        }

        if (c + 2 < 32) {
            int cn = c + 2;
            int s  = cn - (cn / 3) * 3;
            uint32_t so = s * G0_STAGE * 4;
            cp_async16(dA0 + so, XA0 + cn * 16, szA0);
            cp_async16(dA1 + so, XA1 + cn * 16, szA1);
            cp_async16(dB0 + so, WB0 + (size_t)cn * 16 * HID, 16);
            cp_async16(dB1 + so, WB1 + (size_t)cn * 16 * HID, 16);
            cp_commit();
        }
    }

    // epilogue: bias + activation, fp32 store
    #pragma unroll
    for (int mt = 0; mt < 4; mt++) {
        int r0 = rowBase + warpM * 64 + mt * 16 + lr;
        #pragma unroll
        for (int nt = 0; nt < 4; nt++) {
            int cb = nb * 128 + warpN * 32 + nt * 8 + lc * 2;
            float b0 = bias[cb], b1 = bias[cb + 1];
            #pragma unroll
            for (int half = 0; half < 2; half++) {
                int r = r0 + half * 8;
                if (r >= M) continue;
                float v0 = acc[mt][nt][half * 2 + 0] + b0;
                float v1 = acc[mt][nt][half * 2 + 1] + b1;
                if (path == 0) {
                    v0 = (v0 > 0.0f) ? v0 : expm1f(v0);
                    v1 = (v1 > 0.0f) ? v1 : expm1f(v1);
                } else {
                    v0 = fmaxf(v0, 0.0f);
                    v1 = fmaxf(v1, 0.0f);
                }
                *(float2*)(H + (size_t)r * HID + cb) = make_float2(v0, v1);
            }
        }
    }
}

// ---------------- layer-1 via tf32 HMMA, cp.async 3-stage ------------------------
// BM=128, BN=64, K=256 per path; both paths sequential; attn-coupled epilogue.
#define L1_ASTR 20
#define L1_BSTR 72
#define L1_STAGE (128 * L1_ASTR + 16 * L1_BSTR)   // 3712 floats
#define L1_SMEM  (3 * L1_STAGE * 4)               // 44544 bytes

__global__ __launch_bounds__(256) void layer1_mma_kernel(
    const float* __restrict__ Wm1, const float* __restrict__ bm1,
    const float* __restrict__ Wv1, const float* __restrict__ bv1,
    int M)
{
    extern __shared__ float smem[];

    int rowBase = blockIdx.x * 128;
    int t = threadIdx.x, wid = t >> 5, lane = t & 31;
    int warpM = wid >> 2, warpN = wid & 3;
    int lr = lane >> 2, lc = lane & 3;

    int mA0 = t >> 2,        kqA = t & 3;
    int mA1 = (t + 256) >> 2;
    int k2B = t >> 4,        nqB = t & 15;
    int szA0 = (rowBase + mA0 < M) ? 16 : 0;
    int szA1 = (rowBase + mA1 < M) ? 16 : 0;
    uint32_t dA0 = smem_u32(&smem[mA0 * L1_ASTR + kqA * 4]);
    uint32_t dA1 = smem_u32(&smem[mA1 * L1_ASTR + kqA * 4]);
    uint32_t dB  = smem_u32(&smem[128 * L1_ASTR + k2B * L1_BSTR + nqB * 4]);

    float acc0[4][2][4], acc1[4][2][4];
    #pragma unroll
    for (int i = 0; i < 4; i++)
        #pragma unroll
        for (int j = 0; j < 2; j++)
            #pragma unroll
            for (int q = 0; q < 4; q++) { acc0[i][j][q] = 0.f; acc1[i][j][q] = 0.f; }

    #pragma unroll
    for (int p = 0; p < 2; p++) {
        const float* A = p ? g_Hv : g_Hm;
        const float* W = p ? Wv1 : Wm1;
        const float* A0 = A + (size_t)(rowBase + mA0) * HID + kqA * 4;
        const float* A1 = A + (size_t)(rowBase + mA1) * HID + kqA * 4;
        const float* WB = W + (size_t)k2B * CLS + nqB * 4;

        __syncthreads();   // previous path's consumers done before overwrite

        #pragma unroll
        for (int pc = 0; pc < 2; pc++) {
            uint32_t so = pc * L1_STAGE * 4;
            cp_async16(dA0 + so, A0 + pc * 16, szA0);
            cp_async16(dA1 + so, A1 + pc * 16, szA1);
            cp_async16(dB + so, WB + (size_t)pc * 16 * CLS, 16);
            cp_commit();
        }

        for (int c = 0; c < 16; c++) {
            if (c < 14) cp_wait1(); else cp_wait0();
            __syncthreads();

            int cur = c - (c / 3) * 3;
            const float* sA = smem + cur * L1_STAGE;
            const float* sB = sA + 128 * L1_ASTR;

            #pragma unroll
            for (int ks = 0; ks < 2; ks++) {
                int kb = ks * 8;
                uint32_t afr[4][4];
                #pragma unroll
                for (int mt = 0; mt < 4; mt++) {
                    int m0 = warpM * 64 + mt * 16 + lr;
                    afr[mt][0] = __float_as_uint(sA[m0 * L1_ASTR + kb + lc]);
                    afr[mt][1] = __float_as_uint(sA[(m0 + 8) * L1_ASTR + kb + lc]);
                    afr[mt][2] = __float_as_uint(sA[m0 * L1_ASTR + kb + lc + 4]);
                    afr[mt][3] = __float_as_uint(sA[(m0 + 8) * L1_ASTR + kb + lc + 4]);
                }
                #pragma unroll
                for (int nt = 0; nt < 2; nt++) {
                    int n0 = warpN * 16 + nt * 8 + lr;
                    uint32_t bfr[2];
                    bfr[0] = __float_as_uint(sB[(kb + lc) * L1_BSTR + n0]);
                    bfr[1] = __float_as_uint(sB[(kb + lc + 4) * L1_BSTR + n0]);
                    #pragma unroll
                    for (int mt = 0; mt < 4; mt++)
                        mma_tf32(p ? acc1[mt][nt] : acc0[mt][nt], afr[mt], bfr);
                }
            }

            if (c + 2 < 16) {
                int cn = c + 2;
                int s  = cn - (cn / 3) * 3;
                uint32_t so = s * L1_STAGE * 4;
                cp_async16(dA0 + so, A0 + cn * 16, szA0);
                cp_async16(dA1 + so, A1 + cn * 16, szA1);
                cp_async16(dB + so, WB + (size_t)cn * 16 * CLS, 16);
                cp_commit();
            }
        }
    }

    // fused epilogue: elu/relu + attn coupling, write m64/v64
    #pragma unroll
    for (int mt = 0; mt < 4; mt++) {
        int r0 = rowBase + warpM * 64 + mt * 16 + lr;
        #pragma unroll
        for (int nt = 0; nt < 2; nt++) {
            int cb = warpN * 16 + nt * 8 + lc * 2;
            float bm0c = bm1[cb], bm1c = bm1[cb + 1];
            float bv0c = bv1[cb], bv1c = bv1[cb + 1];
            #pragma unroll
            for (int half = 0; half < 2; half++) {
                int r = r0 + half * 8;
                if (r >= M) continue;
                float m0 = acc0[mt][nt][half * 2 + 0] + bm0c;
                float m1 = acc0[mt][nt][half * 2 + 1] + bm1c;
                m0 = (m0 > 0.0f) ? m0 : expm1f(m0);
                m1 = (m1 > 0.0f) ? m1 : expm1f(m1);
                float v0 = fmaxf(acc1[mt][nt][half * 2 + 0] + bv0c, 0.0f) + 1e-6f;
                float v1 = fmaxf(acc1[mt][nt][half * 2 + 1] + bv1c, 0.0f) + 1e-6f;
                float a0 = expf(-v0), a1 = expf(-v1);
                size_t o = (size_t)r * CLS + cb;
                *(float2*)(g_m64 + o) = make_float2(m0 * a0, m1 * a1);
                *(float2*)(g_v64 + o) = make_float2(v0 * a0 * a0, v1 * a1 * a1);
            }
        }
    }
}

// ---------------- fused SpMM (CSR, no atomics) + finalize ----------------------
__global__ __launch_bounds__(256) void spmm_fused_kernel(
    const float* __restrict__ sample, float* __restrict__ out, int n)
{
    int s    = (blockIdx.x * 256 + threadIdx.x) >> 5;
    int lane = threadIdx.x & 31;
    if (s >= n) return;

    float dis_s = g_dis[s], di_s = g_di[s];
    int start = g_rowstart[s];
    int cnt   = g_ecnt[s];
    size_t base = (size_t)s * CLS;

    float am0 = dis_s * dis_s * g_m64[base + lane];
    float am1 = dis_s * dis_s * g_m64[base + 32 + lane];
    float av0 = di_s * di_s * g_v64[base + lane];
    float av1 = di_s * di_s * g_v64[base + 32 + lane];

    int j = 0;
    for (; j + 4 <= cnt; j += 4) {
        int d0 = g_eidx[start + j];
        int d1 = g_eidx[start + j + 1];
        int d2 = g_eidx[start + j + 2];
        int d3 = g_eidx[start + j + 3];
        float wm0 = dis_s * g_dis[d0], wv0 = di_s * g_di[d0];
        float wm1 = dis_s * g_dis[d1], wv1 = di_s * g_di[d1];
        float wm2 = dis_s * g_dis[d2], wv2 = di_s * g_di[d2];
        float wm3 = dis_s * g_dis[d3], wv3 = di_s * g_di[d3];
        size_t b0 = (size_t)d0 * CLS, b1 = (size_t)d1 * CLS;
        size_t b2 = (size_t)d2 * CLS, b3 = (size_t)d3 * CLS;
        am0 += wm0 * g_m64[b0 + lane]      + wm1 * g_m64[b1 + lane]
             + wm2 * g_m64[b2 + lane]      + wm3 * g_m64[b3 + lane];
        am1 += wm0 * g_m64[b0 + 32 + lane] + wm1 * g_m64[b1 + 32 + lane]
             + wm2 * g_m64[b2 + 32 + lane] + wm3 * g_m64[b3 + 32 + lane];
        av0 += wv0 * g_v64[b0 + lane]      + wv1 * g_v64[b1 + lane]
             + wv2 * g_v64[b2 + lane]      + wv3 * g_v64[b3 + lane];
        av1 += wv0 * g_v64[b0 + 32 + lane] + wv1 * g_v64[b1 + 32 + lane]
             + wv2 * g_v64[b2 + 32 + lane] + wv3 * g_v64[b3 + 32 + lane];
    }
    for (; j < cnt; j++) {
        int d = g_eidx[start + j];
        float wm = dis_s * g_dis[d], wv = di_s * g_di[d];
        size_t b = (size_t)d * CLS;
        am0 += wm * g_m64[b + lane];
        am1 += wm * g_m64[b + 32 + lane];
        av0 += wv * g_v64[b + lane];
        av1 += wv * g_v64[b + 32 + lane];
    }

    float va = am0 + sample[base + lane]      * sqrtf(fmaxf(av0, 0.f));
    float vb = am1 + sample[base + 32 + lane] * sqrtf(fmaxf(av1, 0.f));
    float mx = fmaxf(va, vb);
    #pragma unroll
    for (int o = 16; o; o >>= 1) mx = fmaxf(mx, __shfl_xor_sync(0xFFFFFFFFu, mx, o));
    float sum = expf(va - mx) + expf(vb - mx);
    #pragma unroll
    for (int o = 16; o; o >>= 1) sum += __shfl_xor_sync(0xFFFFFFFFu, sum, o);
    float lse = mx + logf(sum);
    out[base + lane]      = va - lse;
    out[base + 32 + lane] = vb - lse;
}

// ---------------- launch ----------------
extern "C" void kernel_launch(void* const* d_in, const int* in_sizes, int n_in,
                              void* d_out, int out_size)
{
    const float* x      = (const float*)d_in[0];
    const float* Wm0    = (const float*)d_in[1];
    const float* bm0    = (const float*)d_in[2];
    const float* Wv0    = (const float*)d_in[3];
    const float* bv0    = (const float*)d_in[4];
    const float* Wm1    = (const float*)d_in[5];
    const float* bm1    = (const float*)d_in[6];
    const float* Wv1    = (const float*)d_in[7];
    const float* bv1    = (const float*)d_in[8];
    const float* sample = (const float*)d_in[9];
    const int*   esrc   = (const int*)d_in[10];
    const int*   edst   = (const int*)d_in[11];
    float* out = (float*)d_out;

    int M = in_sizes[0] / FIN;     // 100000
    int E = in_sizes[10];          // 3200000
    if (M > NNODE) M = NNODE;
    if (E > MAXE)  E = MAXE;
    int nblk = (M + 1023) / 1024;

    cudaFuncSetAttribute(gemm0_mma_kernel, cudaFuncAttributeMaxDynamicSharedMemorySize, G0_SMEM);
    cudaFuncSetAttribute(layer1_mma_kernel, cudaFuncAttributeMaxDynamicSharedMemorySize, L1_SMEM);

    // degree + CSR build
    zero_ecnt_kernel    <<<(M + 255) / 256, 256>>>(M);
    count_edges_kernel  <<<(E + 255) / 256, 256>>>(esrc, E);
    make_deg_kernel     <<<(M + 255) / 256, 256>>>(M);
    scan_blocks_kernel  <<<nblk, 1024>>>(M);
    scan_tops_kernel    <<<1, 128>>>(nblk);
    scan_add_kernel     <<<(M + 255) / 256, 256>>>(M);
    scatter_edges_kernel<<<(E + 255) / 256, 256>>>(esrc, edst, E);

    // dense pipeline
    dim3 g0(4, (M + 127) / 128);
    gemm0_mma_kernel<<<g0, 256, G0_SMEM>>>(x, Wm0, bm0, Wv0, bv0, M);
    layer1_mma_kernel<<<(M + 127) / 128, 256, L1_SMEM>>>(Wm1, bm1, Wv1, bv1, M);

    // graph aggregation + output
    spmm_fused_kernel<<<((size_t)M * 32 + 255) / 256, 256>>>(sample, out, M);
}